// round 13
// baseline (speedup 1.0000x reference)
#include <cuda_runtime.h>
#include <cuda_fp16.h>
#include <cstdint>
#include <math.h>

// ---------------- problem constants ----------------
#define B_SZ 4
#define T_SZ 2048
#define D_SZ 1024
#define M_SZ (B_SZ * T_SZ)
#define MD   ((long)M_SZ * D_SZ)
#define DD   ((long)D_SZ * D_SZ)
#define TT   ((long)T_SZ * T_SZ)
#define TD   ((long)T_SZ * D_SZ)
#define ETA_C 0.1f
#define LCA_SPARSE_ITERS 2
#define LCA_DENSE_ITERS  7

// ---------------- scratch (device globals; no allocation) ----------------
__device__ __half g_u3[3 * M_SZ * D_SZ];     // u_q, u_k, v (fp16)
__device__ __half g_vt[M_SZ * D_SZ];         // V^T per batch [B][D][T] (fp16)
__device__ float  g_vs[2 * M_SZ * D_SZ];     // LCA v-state (fp32)
__device__ __half g_ab[2][2 * M_SZ * D_SZ];  // LCA codes ping-pong x (q,k) (fp16)
__device__ __half g_G2[2 * D_SZ * D_SZ];     // sym zero-diag Gq,Gk (fp16)
__device__ float  g_S[(size_t)B_SZ * T_SZ * T_SZ];   // scores (fp32)
__device__ __half g_Ph[(size_t)B_SZ * T_SZ * T_SZ];  // probs (fp16)
__device__ __half g_o[M_SZ * D_SZ];          // attention out (fp16)
__device__ __half g_xr[M_SZ * D_SZ];         // x (fp16)
__device__ __half g_wqkvr[3 * D_SZ * D_SZ];  // W_qkv (fp16)
__device__ __half g_woutr[D_SZ * D_SZ];      // W_out (fp16)

// ---------------- helpers ----------------
__device__ __forceinline__ uint32_t smem_u32(const void* p) {
    uint32_t a;
    asm("{ .reg .u64 t; cvta.to.shared.u64 t, %1; cvt.u32.u64 %0, t; }" : "=r"(a) : "l"(p));
    return a;
}
__device__ __forceinline__ void cp_async16(uint32_t dst, const void* src) {
    asm volatile("cp.async.cg.shared.global [%0], [%1], 16;" :: "r"(dst), "l"(src));
}
#define CP_COMMIT() asm volatile("cp.async.commit_group;" ::: "memory")
#define CP_WAIT1()  asm volatile("cp.async.wait_group 1;" ::: "memory")
#define CP_WAIT0()  asm volatile("cp.async.wait_group 0;" ::: "memory")

#define LDSM_X4(r, addr) \
    asm volatile("ldmatrix.sync.aligned.m8n8.x4.shared.b16 {%0,%1,%2,%3}, [%4];" \
                 : "=r"((r)[0]), "=r"((r)[1]), "=r"((r)[2]), "=r"((r)[3]) : "r"(addr))

__device__ __forceinline__ void mma_f16(float* c, const uint32_t* a, const uint32_t* b) {
    asm volatile(
        "mma.sync.aligned.m16n8k16.row.col.f32.f16.f16.f32 "
        "{%0,%1,%2,%3}, {%4,%5,%6,%7}, {%8,%9}, {%0,%1,%2,%3};"
        : "+f"(c[0]), "+f"(c[1]), "+f"(c[2]), "+f"(c[3])
        : "r"(a[0]), "r"(a[1]), "r"(a[2]), "r"(a[3]), "r"(b[0]), "r"(b[1]));
}
__device__ __forceinline__ uint32_t h2pack(float a, float b) {
    __half2 h = __floats2half2_rn(a, b);
    return *reinterpret_cast<uint32_t*>(&h);
}
__device__ __forceinline__ float2 h2unpack(uint32_t u) {
    return __half22float2(*reinterpret_cast<__half2*>(&u));
}

// ---------------- GEMM (NT, fp16 in / fp32 acc): C = alpha * A B^T --------------
// NEW shape (crossbar-byte optimized): 256x128 CTA tile, 8 warps in a 4x2 grid
// of 64x64 warp tiles, ONE 256-thread CTA per SM. 0.084 B/MAC vs 0.122 for the
// 128x128 shape. Loop skeleton / ldmatrix addressing / 144B-row bank math are
// identical to the proven R12 kernel.
#define MODE_QKV   0   // C=u fp16; for z<2 also vs=eta*u (fp32), a0=soft (fp16)
#define MODE_LCA   1   // fused LCA prox; writes fp16 a
#define MODE_SCORE 2   // triangular-grid decode; writes fp32 S
#define MODE_PV    3   // causal K-limit; writes fp16 o
#define MODE_PLAIN 4   // writes fp32 out

#define BM     256
#define BN     128
#define BK     64
#define ROWB   144                     // bytes per smem row (128 data + 16 pad)
#define ATILE  (BM * ROWB)             // 36864 B
#define BTILE  (BN * ROWB)             // 18432 B
#define GSMEM_BYTES (2 * (ATILE + BTILE))   // 110592 B

template <int MODE>
__global__ void __launch_bounds__(256, 1)
mm_f16(const __half* __restrict__ A, const __half* __restrict__ Bm, void* __restrict__ Cv,
       int K, int ldA, int ldB, int ldC, float alpha,
       long sA, long sB, long sC,
       const __half* __restrict__ U, float* __restrict__ Vst, __half* __restrict__ Aux,
       const float* __restrict__ llq, const float* __restrict__ llk)
{
    int r0, c0;
    if (MODE == MODE_SCORE) {
        // live tiles: c0 <= r0+BM-1; per 256-row band by: 2by+2 tiles, offset by*(by+1)
        const int t = blockIdx.x;
        int by = 0;
        while ((by + 1) * (by + 2) <= t) by++;
        const int bx = t - by * (by + 1);
        r0 = by * BM; c0 = bx * BN;
    } else {
        r0 = blockIdx.y * BM;
        c0 = blockIdx.x * BN;
    }

    const long bz = blockIdx.z;
    A  += bz * sA;
    Bm += bz * sB;

    extern __shared__ char smem[];
    const uint32_t sbase = smem_u32(smem);

    const int tid  = threadIdx.x;
    const int lane = tid & 31;
    const int wid  = tid >> 5;
    const int wm   = (wid >> 1) * 64;   // warp row offset (0,64,128,192)
    const int wn   = (wid & 1) * 64;    // warp col offset (0,64)
    const int lr   = lane >> 2;         // 0..7
    const int lc   = lane & 3;          // 0..3

    // ldmatrix per-lane address offsets (within a tile)
    const uint32_t a_lm = (uint32_t)(wm + (lane & 15)) * ROWB + (lane & 16);
    const uint32_t b_lm = (uint32_t)(wn + (lane & 7) + ((lane >> 1) & 8)) * ROWB
                        + ((lane << 1) & 16);

    const int kmax = (MODE == MODE_PV) ? min(K, r0 + BM) : K;
    const int nch  = kmax / BK;

    float acc[4][8][4];
#pragma unroll
    for (int i = 0; i < 4; i++)
#pragma unroll
        for (int j = 0; j < 8; j++)
#pragma unroll
            for (int e = 0; e < 4; e++) acc[i][j][e] = 0.f;

    auto issue = [&](int c) {
        const int buf = c & 1;
        const __half* Ac = A  + (long)r0 * ldA + c * BK;
        const __half* Bc = Bm + (long)c0 * ldB + c * BK;
        const uint32_t ab = sbase + buf * ATILE;
        const uint32_t bb = sbase + 2 * ATILE + buf * BTILE;
#pragma unroll
        for (int i = 0; i < 8; i++) {            // A: 2048 16B granules
            const int idx = tid + i * 256;
            const int row = idx >> 3, c8 = idx & 7;
            cp_async16(ab + (uint32_t)(row * ROWB + c8 * 16), Ac + (long)row * ldA + c8 * 8);
        }
#pragma unroll
        for (int i = 0; i < 4; i++) {            // B: 1024 16B granules
            const int idx = tid + i * 256;
            const int row = idx >> 3, c8 = idx & 7;
            cp_async16(bb + (uint32_t)(row * ROWB + c8 * 16), Bc + (long)row * ldB + c8 * 8);
        }
        CP_COMMIT();
    };

    issue(0);
    for (int c = 0; c < nch; c++) {
        if (c + 1 < nch) { issue(c + 1); CP_WAIT1(); }
        else             { CP_WAIT0(); }
        __syncthreads();

        const uint32_t Aad = sbase + (c & 1) * ATILE + a_lm;
        const uint32_t Bad = sbase + 2 * ATILE + (c & 1) * BTILE + b_lm;
#pragma unroll
        for (int g = 0; g < 4; g++) {            // four 16-k groups per chunk
            const uint32_t goff = g * 32;        // bytes
            uint32_t af[4][4], bf[4][4];
#pragma unroll
            for (int mt = 0; mt < 4; mt++)
                LDSM_X4(af[mt], Aad + mt * (16 * ROWB) + goff);
#pragma unroll
            for (int p = 0; p < 4; p++)
                LDSM_X4(bf[p], Bad + p * (16 * ROWB) + goff);
#pragma unroll
            for (int mt = 0; mt < 4; mt++)
#pragma unroll
                for (int nt = 0; nt < 8; nt++)
                    mma_f16(acc[mt][nt], af[mt], &bf[nt >> 1][(nt & 1) * 2]);
        }
        __syncthreads();
    }

    // ---------------- epilogue ----------------
    float lam = 0.f;
    if (MODE == MODE_LCA || (MODE == MODE_QKV && bz < 2))
        lam = expf(bz == 0 ? *llq : *llk);
#pragma unroll
    for (int mt = 0; mt < 4; mt++) {
#pragma unroll
        for (int h = 0; h < 2; h++) {
            const int row = r0 + wm + mt * 16 + lr + h * 8;
#pragma unroll
            for (int nt = 0; nt < 8; nt++) {
                const int col = c0 + wn + nt * 8 + lc * 2;
                const long idx = (long)row * ldC + col;
                float x0 = acc[mt][nt][h * 2 + 0];
                float x1 = acc[mt][nt][h * 2 + 1];
                if (MODE == MODE_LCA) {
                    __half* Ch = (__half*)Cv + bz * sC;
                    float2 u2 = h2unpack(*(const uint32_t*)(U + bz * sC + idx));
                    float2 v2 = *(const float2*)(Vst + bz * sC + idx);
                    float2 vn;
                    vn.x = v2.x + ETA_C * (u2.x - v2.x - x0);
                    vn.y = v2.y + ETA_C * (u2.y - v2.y - x1);
                    *(float2*)(Vst + bz * sC + idx) = vn;
                    float s, o0, o1;
                    s = fabsf(vn.x) - lam; o0 = (s > 0.f) ? copysignf(s, vn.x) : 0.f;
                    s = fabsf(vn.y) - lam; o1 = (s > 0.f) ? copysignf(s, vn.y) : 0.f;
                    *(uint32_t*)(Ch + idx) = h2pack(o0, o1);
                } else if (MODE == MODE_QKV) {
                    __half* Ch = (__half*)Cv + bz * sC;
                    *(uint32_t*)(Ch + idx) = h2pack(x0, x1);         // u (fp16)
                    if (bz < 2) {                                    // fused LCA iter 1
                        float2 vn = make_float2(ETA_C * x0, ETA_C * x1);
                        *(float2*)(Vst + bz * sC + idx) = vn;
                        float s, o0, o1;
                        s = fabsf(vn.x) - lam; o0 = (s > 0.f) ? copysignf(s, vn.x) : 0.f;
                        s = fabsf(vn.y) - lam; o1 = (s > 0.f) ? copysignf(s, vn.y) : 0.f;
                        *(uint32_t*)(Aux + bz * sC + idx) = h2pack(o0, o1);
                    }
                } else if (MODE == MODE_PV) {
                    __half* Ch = (__half*)Cv + bz * sC;
                    *(uint32_t*)(Ch + idx) = h2pack(x0, x1);
                } else {  // SCORE / PLAIN -> fp32
                    float* Cf = (float*)Cv + bz * sC;
                    *(float2*)(Cf + idx) = make_float2(alpha * x0, alpha * x1);
                }
            }
        }
    }
}

// ---------------- sparse LCA iteration: warp per row (fp16 a/G/u) -------------
__global__ void __launch_bounds__(256, 4)
lca_sparse(const __half* __restrict__ a_in, const __half* __restrict__ G2,
           const __half* __restrict__ U, float* __restrict__ Vst,
           __half* __restrict__ a_out,
           const float* __restrict__ llq, const float* __restrict__ llk)
{
    const long row  = ((long)blockIdx.x * blockDim.x + threadIdx.x) >> 5;
    const int  lane = threadIdx.x & 31;
    const int  half = (row >= M_SZ);
    const __half* G = G2 + (long)half * DD;
    const float lam = expf(half ? *llk : *llq);

    const __half* arow = a_in + row * D_SZ;

    float acc[8][4];
#pragma unroll
    for (int j = 0; j < 8; j++)
#pragma unroll
        for (int i = 0; i < 4; i++) acc[j][i] = 0.f;

#pragma unroll
    for (int j = 0; j < 8; j++) {
        const __half2* ap = (const __half2*)(arow + lane * 4 + 128 * j);
        const float2 f0 = __half22float2(ap[0]);
        const float2 f1 = __half22float2(ap[1]);
        const float vals[4] = { f0.x, f0.y, f1.x, f1.y };
#pragma unroll
        for (int i = 0; i < 4; i++) {
            unsigned m = __ballot_sync(0xFFFFFFFFu, vals[i] != 0.f);
            while (m) {
                const int s = __ffs(m) - 1;
                m &= m - 1;
                const float aval = __shfl_sync(0xFFFFFFFFu, vals[i], s);
                const int k = s * 4 + 128 * j + i;
                const __half* Gr = G + (long)k * D_SZ + lane * 4;
#pragma unroll
                for (int jj = 0; jj < 8; jj++) {
                    const __half2* gp = (const __half2*)(Gr + 128 * jj);
                    const float2 g0 = __half22float2(gp[0]);
                    const float2 g1 = __half22float2(gp[1]);
                    acc[jj][0] += aval * g0.x;
                    acc[jj][1] += aval * g0.y;
                    acc[jj][2] += aval * g1.x;
                    acc[jj][3] += aval * g1.y;
                }
            }
        }
    }

    const __half* urow = U + row * D_SZ;
    float* vrow = Vst + row * D_SZ;
    __half* orow = a_out + row * D_SZ;
#pragma unroll
    for (int j = 0; j < 8; j++) {
        const int c = lane * 4 + 128 * j;
        const __half2* up = (const __half2*)(urow + c);
        const float2 u0 = __half22float2(up[0]);
        const float2 u1 = __half22float2(up[1]);
        const float4 vv = *(const float4*)(vrow + c);
        float4 vn;
        vn.x = vv.x + ETA_C * (u0.x - vv.x - acc[j][0]);
        vn.y = vv.y + ETA_C * (u0.y - vv.y - acc[j][1]);
        vn.z = vv.z + ETA_C * (u1.x - vv.z - acc[j][2]);
        vn.w = vv.w + ETA_C * (u1.y - vv.w - acc[j][3]);
        *(float4*)(vrow + c) = vn;
        float s, o0, o1, o2, o3;
        s = fabsf(vn.x) - lam; o0 = (s > 0.f) ? copysignf(s, vn.x) : 0.f;
        s = fabsf(vn.y) - lam; o1 = (s > 0.f) ? copysignf(s, vn.y) : 0.f;
        s = fabsf(vn.z) - lam; o2 = (s > 0.f) ? copysignf(s, vn.z) : 0.f;
        s = fabsf(vn.w) - lam; o3 = (s > 0.f) ? copysignf(s, vn.w) : 0.f;
        uint2 pk = make_uint2(h2pack(o0, o1), h2pack(o2, o3));
        *(uint2*)(orow + c) = pk;
    }
}

// ---------------- small kernels ----------------
__global__ void round_copy_h(const float* __restrict__ in, __half* __restrict__ out)
{
    const long i = ((long)blockIdx.x * blockDim.x + threadIdx.x) * 4;
    float4 v = *(const float4*)(in + i);
    uint2 pk = make_uint2(h2pack(v.x, v.y), h2pack(v.z, v.w));
    *(uint2*)(out + i) = pk;
}

__global__ void symzero2(const float* __restrict__ Gq, const float* __restrict__ Gk,
                         __half* __restrict__ Gs)
{
    const long idx = (long)blockIdx.x * blockDim.x + threadIdx.x;
    const long e = idx & (DD - 1);
    const float* G = (idx < DD) ? Gq : Gk;
    const int i = (int)(e / D_SZ), j = (int)(e % D_SZ);
    Gs[idx] = (i == j) ? __float2half_rn(0.f)
                       : __float2half_rn(0.5f * (G[e] + G[(long)j * D_SZ + i]));
}

// V [B][T][D] fp16 -> Vt [B][D][T] fp16
__global__ void transpose_bt(const __half* __restrict__ in, __half* __restrict__ out)
{
    __shared__ float t[32][33];
    const int b = blockIdx.z;
    const int t0 = blockIdx.x * 32, d0 = blockIdx.y * 32;
    in  += (long)b * TD;
    out += (long)b * TD;
    const int x = threadIdx.x, y = threadIdx.y;
#pragma unroll
    for (int i = 0; i < 32; i += 8)
        t[y + i][x] = __half2float(in[(long)(t0 + y + i) * D_SZ + d0 + x]);
    __syncthreads();
#pragma unroll
    for (int i = 0; i < 32; i += 8)
        out[(long)(d0 + y + i) * T_SZ + t0 + x] = __float2half_rn(t[x][y + i]);
}

// causal softmax: reads fp32 scores S, writes fp16 probs Ph (tail zeroed)
__global__ void softmax_causal(const float* __restrict__ S, __half* __restrict__ Ph)
{
    const int i = blockIdx.x;
    const int b = blockIdx.y;
    const float* row = S + ((long)b * T_SZ + i) * T_SZ;
    __half* prow = Ph + ((long)b * T_SZ + i) * T_SZ;
    const int tid = threadIdx.x;
    const int n = i + 1;
    __shared__ float red[256];

    float mx = -INFINITY;
    for (int j = tid; j < n; j += 256) mx = fmaxf(mx, row[j]);
    red[tid] = mx;
    __syncthreads();
    for (int s = 128; s > 0; s >>= 1) {
        if (tid < s) red[tid] = fmaxf(red[tid], red[tid + s]);
        __syncthreads();
    }
    mx = red[0];
    __syncthreads();

    float sum = 0.f;
    for (int j = tid; j < n; j += 256) {
        float e = expf(row[j] - mx);
        prow[j] = __float2half_rn(e);
        sum += e;
    }
    red[tid] = sum;
    __syncthreads();
    for (int s = 128; s > 0; s >>= 1) {
        if (tid < s) red[tid] += red[tid + s];
        __syncthreads();
    }
    const float inv = 1.f / red[0];
    for (int j = tid; j < n; j += 256)
        prow[j] = __float2half_rn(__half2float(prow[j]) * inv);
    for (int j = n + tid; j < T_SZ; j += 256) prow[j] = __float2half_rn(0.f);
}

// ---------------- launch ----------------
extern "C" void kernel_launch(void* const* d_in, const int* in_sizes, int n_in,
                              void* d_out, int out_size)
{
    const float* x        = (const float*)d_in[0];
    const float* W_qkv    = (const float*)d_in[1];
    const float* W_out    = (const float*)d_in[2];
    const float* Gq_raw   = (const float*)d_in[3];
    const float* loglam_q = (const float*)d_in[4];
    const float* Gk_raw   = (const float*)d_in[5];
    const float* loglam_k = (const float*)d_in[6];
    float* out = (float*)d_out;
    (void)in_sizes; (void)n_in; (void)out_size;

    float *vs, *S;
    __half *u3, *vt, *abb, *G2h, *Ph, *o, *xr, *wqr, *wor;
    cudaGetSymbolAddress((void**)&u3,  g_u3);
    cudaGetSymbolAddress((void**)&vt,  g_vt);
    cudaGetSymbolAddress((void**)&vs,  g_vs);
    cudaGetSymbolAddress((void**)&abb, g_ab);
    cudaGetSymbolAddress((void**)&G2h, g_G2);
    cudaGetSymbolAddress((void**)&S,   g_S);
    cudaGetSymbolAddress((void**)&Ph,  g_Ph);
    cudaGetSymbolAddress((void**)&o,   g_o);
    cudaGetSymbolAddress((void**)&xr,  g_xr);
    cudaGetSymbolAddress((void**)&wqr, g_wqkvr);
    cudaGetSymbolAddress((void**)&wor, g_woutr);

    cudaFuncSetAttribute(mm_f16<MODE_QKV>,   cudaFuncAttributeMaxDynamicSharedMemorySize, GSMEM_BYTES);
    cudaFuncSetAttribute(mm_f16<MODE_LCA>,   cudaFuncAttributeMaxDynamicSharedMemorySize, GSMEM_BYTES);
    cudaFuncSetAttribute(mm_f16<MODE_SCORE>, cudaFuncAttributeMaxDynamicSharedMemorySize, GSMEM_BYTES);
    cudaFuncSetAttribute(mm_f16<MODE_PV>,    cudaFuncAttributeMaxDynamicSharedMemorySize, GSMEM_BYTES);
    cudaFuncSetAttribute(mm_f16<MODE_PLAIN>, cudaFuncAttributeMaxDynamicSharedMemorySize, GSMEM_BYTES);

    __half* ab[2] = { abb, abb + 2 * MD };
    __half* vvv = u3 + 2 * MD;

    const dim3 thr(256);

    // 0) pre-round raw GEMM inputs to fp16
    round_copy_h<<<(unsigned)(MD / 1024), thr>>>(x, xr);
    round_copy_h<<<(unsigned)(3 * DD / 1024), thr>>>(W_qkv, wqr);
    round_copy_h<<<(unsigned)(DD / 1024), thr>>>(W_out, wor);

    // 1) symmetrize + zero-diag both G's (fp16)
    symzero2<<<(unsigned)(2 * DD / 256), thr>>>(Gq_raw, Gk_raw, G2h);

    // 2) QKV projections + fused LCA iteration 1 (z<2 writes vs, a0)
    {
        dim3 g(D_SZ / BN, M_SZ / BM, 3);
        mm_f16<MODE_QKV><<<g, thr, GSMEM_BYTES>>>(xr, wqr, u3, D_SZ, D_SZ, D_SZ, D_SZ, 1.f,
                                                  0, DD, MD, nullptr, vs, ab[0],
                                                  loglam_q, loglam_k);
    }

    // 3) transpose V (fp16)
    {
        dim3 g(T_SZ / 32, D_SZ / 32, B_SZ);
        transpose_bt<<<g, dim3(32, 8)>>>(vvv, vt);
    }

    // 4) LCA iterations 2..3: SPARSE (a nearly empty)
    int cur = 0;
    {
        const unsigned g = (unsigned)(2 * M_SZ / 8);   // warp per row, 8 warps/CTA
        for (int it = 0; it < LCA_SPARSE_ITERS; it++) {
            lca_sparse<<<g, thr>>>(ab[cur], G2h, u3, vs, ab[cur ^ 1], loglam_q, loglam_k);
            cur ^= 1;
        }
    }

    // 5) LCA iterations 4..10: dense fp16 tensor GEMM + prox, q+k merged over z
    {
        dim3 g(D_SZ / BN, M_SZ / BM, 2);
        for (int it = 0; it < LCA_DENSE_ITERS; it++) {
            mm_f16<MODE_LCA><<<g, thr, GSMEM_BYTES>>>(ab[cur], G2h, ab[cur ^ 1],
                                                      D_SZ, D_SZ, D_SZ, D_SZ, 1.f,
                                                      MD, DD, MD, u3, vs, nullptr,
                                                      loglam_q, loglam_k);
            cur ^= 1;
        }
    }
    __half* qf = ab[cur];
    __half* kf = ab[cur] + MD;

    // 6) scores S = q k^T / 32, triangular grid (72 live 256x128 tiles x batch)
    {
        dim3 g(72, 1, B_SZ);
        mm_f16<MODE_SCORE><<<g, thr, GSMEM_BYTES>>>(qf, kf, S, D_SZ, D_SZ, D_SZ, T_SZ, 0.03125f,
                                                    TD, TD, TT, nullptr, nullptr, nullptr,
                                                    nullptr, nullptr);
    }

    // 7) causal softmax: fp32 scores -> fp16 probs
    {
        dim3 g(T_SZ, B_SZ);
        softmax_causal<<<g, thr>>>(S, Ph);
    }

    // 8) o = P @ V (NT against Vt, causal K-limit), fp16 out
    {
        dim3 g(D_SZ / BN, T_SZ / BM, B_SZ);
        mm_f16<MODE_PV><<<g, thr, GSMEM_BYTES>>>(Ph, vt, o, T_SZ, T_SZ, T_SZ, D_SZ, 1.f,
                                                 TT, TD, TD, nullptr, nullptr, nullptr,
                                                 nullptr, nullptr);
    }

    // 9) out = o @ W_out^T (fp32 output)
    {
        dim3 g(D_SZ / BN, M_SZ / BM, 1);
        mm_f16<MODE_PLAIN><<<g, thr, GSMEM_BYTES>>>(o, wor, out, D_SZ, D_SZ, D_SZ, D_SZ, 1.f,
                                                    0, 0, 0, nullptr, nullptr, nullptr,
                                                    nullptr, nullptr);
    }
}

// round 14
// speedup vs baseline: 1.3483x; 1.3483x over previous
#include <cuda_runtime.h>
#include <cuda_fp16.h>
#include <cstdint>
#include <math.h>

// ---------------- problem constants ----------------
#define B_SZ 4
#define T_SZ 2048
#define D_SZ 1024
#define M_SZ (B_SZ * T_SZ)
#define MD   ((long)M_SZ * D_SZ)
#define DD   ((long)D_SZ * D_SZ)
#define TT   ((long)T_SZ * T_SZ)
#define TD   ((long)T_SZ * D_SZ)
#define ETA_C 0.1f
#define LCA_SPARSE_ITERS 2
#define LCA_DENSE_ITERS  7

// ---------------- scratch (device globals; no allocation) ----------------
__device__ __half g_u3[3 * M_SZ * D_SZ];     // u_q, u_k, v (fp16)
__device__ __half g_vt[M_SZ * D_SZ];         // V^T per batch [B][D][T] (fp16)
__device__ float  g_vs[2 * M_SZ * D_SZ];     // LCA v-state (fp32)
__device__ __half g_ab[2][2 * M_SZ * D_SZ];  // LCA codes ping-pong x (q,k) (fp16)
__device__ __half g_G2[2 * D_SZ * D_SZ];     // sym zero-diag Gq,Gk (fp16)
__device__ float  g_S[(size_t)B_SZ * T_SZ * T_SZ];   // scores (fp32)
__device__ __half g_Ph[(size_t)B_SZ * T_SZ * T_SZ];  // probs (fp16)
__device__ __half g_o[M_SZ * D_SZ];          // attention out (fp16)
__device__ __half g_xr[M_SZ * D_SZ];         // x (fp16)
__device__ __half g_wqkvr[3 * D_SZ * D_SZ];  // W_qkv (fp16)
__device__ __half g_woutr[D_SZ * D_SZ];      // W_out (fp16)

// ---------------- helpers ----------------
__device__ __forceinline__ uint32_t smem_u32(const void* p) {
    uint32_t a;
    asm("{ .reg .u64 t; cvta.to.shared.u64 t, %1; cvt.u32.u64 %0, t; }" : "=r"(a) : "l"(p));
    return a;
}
__device__ __forceinline__ void cp_async16(uint32_t dst, const void* src) {
    asm volatile("cp.async.cg.shared.global [%0], [%1], 16;" :: "r"(dst), "l"(src));
}
#define CP_COMMIT() asm volatile("cp.async.commit_group;" ::: "memory")
#define CP_WAIT1()  asm volatile("cp.async.wait_group 1;" ::: "memory")
#define CP_WAIT0()  asm volatile("cp.async.wait_group 0;" ::: "memory")

#define LDSM_X4(r, addr) \
    asm volatile("ldmatrix.sync.aligned.m8n8.x4.shared.b16 {%0,%1,%2,%3}, [%4];" \
                 : "=r"((r)[0]), "=r"((r)[1]), "=r"((r)[2]), "=r"((r)[3]) : "r"(addr))

__device__ __forceinline__ void mma_f16(float* c, const uint32_t* a, const uint32_t* b) {
    asm volatile(
        "mma.sync.aligned.m16n8k16.row.col.f32.f16.f16.f32 "
        "{%0,%1,%2,%3}, {%4,%5,%6,%7}, {%8,%9}, {%0,%1,%2,%3};"
        : "+f"(c[0]), "+f"(c[1]), "+f"(c[2]), "+f"(c[3])
        : "r"(a[0]), "r"(a[1]), "r"(a[2]), "r"(a[3]), "r"(b[0]), "r"(b[1]));
}
__device__ __forceinline__ uint32_t h2pack(float a, float b) {
    __half2 h = __floats2half2_rn(a, b);
    return *reinterpret_cast<uint32_t*>(&h);
}
__device__ __forceinline__ float2 h2unpack(uint32_t u) {
    return __half22float2(*reinterpret_cast<__half2*>(&u));
}

// ---------------- GEMM (NT, fp16 in / fp32 acc): C = alpha * A B^T --------------
// PROVEN R12 shape: 128x128 CTA tile, 8 warps of 64x32, 2 CTAs/SM, BK=64,
// ldmatrix.x4 fragments from natural 144B-row layout (conflict-free).
// NEW: 3-stage cp.async pipeline (2 chunks in flight) + ONE barrier per chunk.
#define MODE_QKV   0   // C=u fp16; for z<2 also vs=eta*u (fp32), a0=soft (fp16)
#define MODE_LCA   1   // fused LCA prox; writes fp16 a
#define MODE_SCORE 2   // triangular-grid decode; writes fp32 S
#define MODE_PV    3   // causal K-limit; writes fp16 o
#define MODE_PLAIN 4   // writes fp32 out

#define BK     64
#define ROWB   144                       // bytes per smem row (128 data + 16 pad)
#define ATILE  (128 * ROWB)              // 18432 B per operand tile
#define STAGE_B (2 * ATILE)              // A + B per stage = 36864 B
#define NSTAGE 3
#define GSMEM_BYTES (NSTAGE * STAGE_B)   // 110592 B (2 CTAs/SM -> 216 KB)

template <int MODE>
__global__ void __launch_bounds__(256, 2)
mm_f16(const __half* __restrict__ A, const __half* __restrict__ Bm, void* __restrict__ Cv,
       int K, int ldA, int ldB, int ldC, float alpha,
       long sA, long sB, long sC,
       const __half* __restrict__ U, float* __restrict__ Vst, __half* __restrict__ Aux,
       const float* __restrict__ llq, const float* __restrict__ llk)
{
    int r0, c0;
    if (MODE == MODE_SCORE) {
        const int t = blockIdx.x;                 // t = by*(by+1)/2 + bx, bx<=by
        int by = (int)((sqrtf(8.f * t + 1.f) - 1.f) * 0.5f);
        while ((by + 1) * (by + 2) / 2 <= t) by++;
        while (by * (by + 1) / 2 > t) by--;
        const int bx = t - by * (by + 1) / 2;
        r0 = by * 128; c0 = bx * 128;
    } else {
        r0 = blockIdx.y * 128;
        c0 = blockIdx.x * 128;
    }

    const long bz = blockIdx.z;
    A  += bz * sA;
    Bm += bz * sB;

    extern __shared__ char smem[];
    const uint32_t sbase = smem_u32(smem);

    const int tid  = threadIdx.x;
    const int lane = tid & 31;
    const int wid  = tid >> 5;
    const int wm   = (wid >> 2) * 64;
    const int wn   = (wid & 3) * 32;
    const int lr   = lane >> 2;         // 0..7
    const int lc   = lane & 3;          // 0..3

    const uint32_t a_lm = (uint32_t)(wm + (lane & 15)) * ROWB + (lane & 16);
    const uint32_t b_lm = (uint32_t)(wn + (lane & 7) + ((lane >> 1) & 8)) * ROWB
                        + ((lane << 1) & 16);

    const int kmax = (MODE == MODE_PV) ? min(K, r0 + 128) : K;
    const int nch  = kmax / BK;          // >= 2 for all uses

    float acc[4][4][4];
#pragma unroll
    for (int i = 0; i < 4; i++)
#pragma unroll
        for (int j = 0; j < 4; j++)
#pragma unroll
            for (int e = 0; e < 4; e++) acc[i][j][e] = 0.f;

    auto issue = [&](int c) {
        const int stg = c % NSTAGE;
        const __half* Ac = A  + (long)r0 * ldA + c * BK;
        const __half* Bc = Bm + (long)c0 * ldB + c * BK;
        const uint32_t ab = sbase + stg * STAGE_B;
        const uint32_t bb = ab + ATILE;
#pragma unroll
        for (int i = 0; i < 4; i++) {
            const int idx = tid + i * 256;       // 1024 16B granules per tile
            const int row = idx >> 3, c8 = idx & 7;
            cp_async16(ab + (uint32_t)(row * ROWB + c8 * 16), Ac + (long)row * ldA + c8 * 8);
            cp_async16(bb + (uint32_t)(row * ROWB + c8 * 16), Bc + (long)row * ldB + c8 * 8);
        }
        CP_COMMIT();
    };

    issue(0);
    issue(1);
    for (int c = 0; c < nch; c++) {
        if (c + 1 < nch) CP_WAIT1(); else CP_WAIT0();
        __syncthreads();                 // group c landed; stage (c-1)%3 free for reuse
        if (c + 2 < nch) issue(c + 2);   // targets stage (c+2)%3 == (c-1)%3

        const uint32_t sb = sbase + (c % NSTAGE) * STAGE_B;
        const uint32_t Aad = sb + a_lm;
        const uint32_t Bad = sb + ATILE + b_lm;
#pragma unroll
        for (int g = 0; g < 4; g++) {    // four 16-k groups per chunk
            const uint32_t goff = g * 32;
            uint32_t af[4][4], bf[2][4];
#pragma unroll
            for (int mt = 0; mt < 4; mt++)
                LDSM_X4(af[mt], Aad + mt * (16 * ROWB) + goff);
#pragma unroll
            for (int p = 0; p < 2; p++)
                LDSM_X4(bf[p], Bad + p * (16 * ROWB) + goff);
#pragma unroll
            for (int mt = 0; mt < 4; mt++)
#pragma unroll
                for (int nt = 0; nt < 4; nt++)
                    mma_f16(acc[mt][nt], af[mt], &bf[nt >> 1][(nt & 1) * 2]);
        }
    }

    // ---------------- epilogue ----------------
    float lam = 0.f;
    if (MODE == MODE_LCA || (MODE == MODE_QKV && bz < 2))
        lam = expf(bz == 0 ? *llq : *llk);
#pragma unroll
    for (int mt = 0; mt < 4; mt++) {
#pragma unroll
        for (int h = 0; h < 2; h++) {
            const int row = r0 + wm + mt * 16 + lr + h * 8;
#pragma unroll
            for (int nt = 0; nt < 4; nt++) {
                const int col = c0 + wn + nt * 8 + lc * 2;
                const long idx = (long)row * ldC + col;
                float x0 = acc[mt][nt][h * 2 + 0];
                float x1 = acc[mt][nt][h * 2 + 1];
                if (MODE == MODE_LCA) {
                    __half* Ch = (__half*)Cv + bz * sC;
                    float2 u2 = h2unpack(*(const uint32_t*)(U + bz * sC + idx));
                    float2 v2 = *(const float2*)(Vst + bz * sC + idx);
                    float2 vn;
                    vn.x = v2.x + ETA_C * (u2.x - v2.x - x0);
                    vn.y = v2.y + ETA_C * (u2.y - v2.y - x1);
                    *(float2*)(Vst + bz * sC + idx) = vn;
                    float s, o0, o1;
                    s = fabsf(vn.x) - lam; o0 = (s > 0.f) ? copysignf(s, vn.x) : 0.f;
                    s = fabsf(vn.y) - lam; o1 = (s > 0.f) ? copysignf(s, vn.y) : 0.f;
                    *(uint32_t*)(Ch + idx) = h2pack(o0, o1);
                } else if (MODE == MODE_QKV) {
                    __half* Ch = (__half*)Cv + bz * sC;
                    *(uint32_t*)(Ch + idx) = h2pack(x0, x1);         // u (fp16)
                    if (bz < 2) {                                    // fused LCA iter 1
                        float2 vn = make_float2(ETA_C * x0, ETA_C * x1);
                        *(float2*)(Vst + bz * sC + idx) = vn;
                        float s, o0, o1;
                        s = fabsf(vn.x) - lam; o0 = (s > 0.f) ? copysignf(s, vn.x) : 0.f;
                        s = fabsf(vn.y) - lam; o1 = (s > 0.f) ? copysignf(s, vn.y) : 0.f;
                        *(uint32_t*)(Aux + bz * sC + idx) = h2pack(o0, o1);
                    }
                } else if (MODE == MODE_PV) {
                    __half* Ch = (__half*)Cv + bz * sC;
                    *(uint32_t*)(Ch + idx) = h2pack(x0, x1);
                } else {  // SCORE / PLAIN -> fp32
                    float* Cf = (float*)Cv + bz * sC;
                    *(float2*)(Cf + idx) = make_float2(alpha * x0, alpha * x1);
                }
            }
        }
    }
}

// ---------------- sparse LCA iteration: warp per row (fp16 a/G/u) -------------
__global__ void __launch_bounds__(256, 4)
lca_sparse(const __half* __restrict__ a_in, const __half* __restrict__ G2,
           const __half* __restrict__ U, float* __restrict__ Vst,
           __half* __restrict__ a_out,
           const float* __restrict__ llq, const float* __restrict__ llk)
{
    const long row  = ((long)blockIdx.x * blockDim.x + threadIdx.x) >> 5;
    const int  lane = threadIdx.x & 31;
    const int  half = (row >= M_SZ);
    const __half* G = G2 + (long)half * DD;
    const float lam = expf(half ? *llk : *llq);

    const __half* arow = a_in + row * D_SZ;

    float acc[8][4];
#pragma unroll
    for (int j = 0; j < 8; j++)
#pragma unroll
        for (int i = 0; i < 4; i++) acc[j][i] = 0.f;

#pragma unroll
    for (int j = 0; j < 8; j++) {
        const __half2* ap = (const __half2*)(arow + lane * 4 + 128 * j);
        const float2 f0 = __half22float2(ap[0]);
        const float2 f1 = __half22float2(ap[1]);
        const float vals[4] = { f0.x, f0.y, f1.x, f1.y };
#pragma unroll
        for (int i = 0; i < 4; i++) {
            unsigned m = __ballot_sync(0xFFFFFFFFu, vals[i] != 0.f);
            while (m) {
                const int s = __ffs(m) - 1;
                m &= m - 1;
                const float aval = __shfl_sync(0xFFFFFFFFu, vals[i], s);
                const int k = s * 4 + 128 * j + i;
                const __half* Gr = G + (long)k * D_SZ + lane * 4;
#pragma unroll
                for (int jj = 0; jj < 8; jj++) {
                    const __half2* gp = (const __half2*)(Gr + 128 * jj);
                    const float2 g0 = __half22float2(gp[0]);
                    const float2 g1 = __half22float2(gp[1]);
                    acc[jj][0] += aval * g0.x;
                    acc[jj][1] += aval * g0.y;
                    acc[jj][2] += aval * g1.x;
                    acc[jj][3] += aval * g1.y;
                }
            }
        }
    }

    const __half* urow = U + row * D_SZ;
    float* vrow = Vst + row * D_SZ;
    __half* orow = a_out + row * D_SZ;
#pragma unroll
    for (int j = 0; j < 8; j++) {
        const int c = lane * 4 + 128 * j;
        const __half2* up = (const __half2*)(urow + c);
        const float2 u0 = __half22float2(up[0]);
        const float2 u1 = __half22float2(up[1]);
        const float4 vv = *(const float4*)(vrow + c);
        float4 vn;
        vn.x = vv.x + ETA_C * (u0.x - vv.x - acc[j][0]);
        vn.y = vv.y + ETA_C * (u0.y - vv.y - acc[j][1]);
        vn.z = vv.z + ETA_C * (u1.x - vv.z - acc[j][2]);
        vn.w = vv.w + ETA_C * (u1.y - vv.w - acc[j][3]);
        *(float4*)(vrow + c) = vn;
        float s, o0, o1, o2, o3;
        s = fabsf(vn.x) - lam; o0 = (s > 0.f) ? copysignf(s, vn.x) : 0.f;
        s = fabsf(vn.y) - lam; o1 = (s > 0.f) ? copysignf(s, vn.y) : 0.f;
        s = fabsf(vn.z) - lam; o2 = (s > 0.f) ? copysignf(s, vn.z) : 0.f;
        s = fabsf(vn.w) - lam; o3 = (s > 0.f) ? copysignf(s, vn.w) : 0.f;
        uint2 pk = make_uint2(h2pack(o0, o1), h2pack(o2, o3));
        *(uint2*)(orow + c) = pk;
    }
}

// ---------------- small kernels ----------------
// single launch: rounds x (MD), W_qkv (3*DD), W_out (DD) to fp16
__global__ void round_all(const float* __restrict__ x, const float* __restrict__ wq,
                          const float* __restrict__ wo,
                          __half* __restrict__ xr, __half* __restrict__ wqr,
                          __half* __restrict__ wor)
{
    const long i = ((long)blockIdx.x * blockDim.x + threadIdx.x) * 4;
    const float* in; __half* out; long off;
    if (i < MD)               { in = x;  out = xr;  off = i; }
    else if (i < MD + 3 * DD) { in = wq; out = wqr; off = i - MD; }
    else                      { in = wo; out = wor; off = i - MD - 3 * DD; }
    float4 v = *(const float4*)(in + off);
    uint2 pk = make_uint2(h2pack(v.x, v.y), h2pack(v.z, v.w));
    *(uint2*)(out + off) = pk;
}

__global__ void symzero2(const float* __restrict__ Gq, const float* __restrict__ Gk,
                         __half* __restrict__ Gs)
{
    const long idx = (long)blockIdx.x * blockDim.x + threadIdx.x;
    const long e = idx & (DD - 1);
    const float* G = (idx < DD) ? Gq : Gk;
    const int i = (int)(e / D_SZ), j = (int)(e % D_SZ);
    Gs[idx] = (i == j) ? __float2half_rn(0.f)
                       : __float2half_rn(0.5f * (G[e] + G[(long)j * D_SZ + i]));
}

// V [B][T][D] fp16 -> Vt [B][D][T] fp16
__global__ void transpose_bt(const __half* __restrict__ in, __half* __restrict__ out)
{
    __shared__ float t[32][33];
    const int b = blockIdx.z;
    const int t0 = blockIdx.x * 32, d0 = blockIdx.y * 32;
    in  += (long)b * TD;
    out += (long)b * TD;
    const int x = threadIdx.x, y = threadIdx.y;
#pragma unroll
    for (int i = 0; i < 32; i += 8)
        t[y + i][x] = __half2float(in[(long)(t0 + y + i) * D_SZ + d0 + x]);
    __syncthreads();
#pragma unroll
    for (int i = 0; i < 32; i += 8)
        out[(long)(d0 + y + i) * T_SZ + t0 + x] = __float2half_rn(t[x][y + i]);
}

// single-pass causal softmax: read S once, keep exp in regs, write fp16 probs once
__global__ void softmax_causal(const float* __restrict__ S, __half* __restrict__ Ph)
{
    const int i = blockIdx.x;
    const int b = blockIdx.y;
    const float* row = S + ((long)b * T_SZ + i) * T_SZ;
    __half* prow = Ph + ((long)b * T_SZ + i) * T_SZ;
    const int tid = threadIdx.x;
    const int n = i + 1;
    __shared__ float red[256];

    float v[8];                 // up to 2048/256 = 8 elements per thread
    int cnt = 0;
    float mx = -INFINITY;
    for (int j = tid; j < n; j += 256) { v[cnt++] = row[j]; mx = fmaxf(mx, v[cnt - 1]); }

    red[tid] = mx;
    __syncthreads();
    for (int s = 128; s > 0; s >>= 1) {
        if (tid < s) red[tid] = fmaxf(red[tid], red[tid + s]);
        __syncthreads();
    }
    mx = red[0];
    __syncthreads();

    float sum = 0.f;
#pragma unroll
    for (int c = 0; c < 8; c++)
        if (c < cnt) { v[c] = expf(v[c] - mx); sum += v[c]; }
    red[tid] = sum;
    __syncthreads();
    for (int s = 128; s > 0; s >>= 1) {
        if (tid < s) red[tid] += red[tid + s];
        __syncthreads();
    }
    const float inv = 1.f / red[0];

    int c = 0;
    for (int j = tid; j < n; j += 256) prow[j] = __float2half_rn(v[c++] * inv);
    for (int j = n + tid; j < T_SZ; j += 256) prow[j] = __float2half_rn(0.f);
}

// ---------------- launch ----------------
extern "C" void kernel_launch(void* const* d_in, const int* in_sizes, int n_in,
                              void* d_out, int out_size)
{
    const float* x        = (const float*)d_in[0];
    const float* W_qkv    = (const float*)d_in[1];
    const float* W_out    = (const float*)d_in[2];
    const float* Gq_raw   = (const float*)d_in[3];
    const float* loglam_q = (const float*)d_in[4];
    const float* Gk_raw   = (const float*)d_in[5];
    const float* loglam_k = (const float*)d_in[6];
    float* out = (float*)d_out;
    (void)in_sizes; (void)n_in; (void)out_size;

    float *vs, *S;
    __half *u3, *vt, *abb, *G2h, *Ph, *o, *xr, *wqr, *wor;
    cudaGetSymbolAddress((void**)&u3,  g_u3);
    cudaGetSymbolAddress((void**)&vt,  g_vt);
    cudaGetSymbolAddress((void**)&vs,  g_vs);
    cudaGetSymbolAddress((void**)&abb, g_ab);
    cudaGetSymbolAddress((void**)&G2h, g_G2);
    cudaGetSymbolAddress((void**)&S,   g_S);
    cudaGetSymbolAddress((void**)&Ph,  g_Ph);
    cudaGetSymbolAddress((void**)&o,   g_o);
    cudaGetSymbolAddress((void**)&xr,  g_xr);
    cudaGetSymbolAddress((void**)&wqr, g_wqkvr);
    cudaGetSymbolAddress((void**)&wor, g_woutr);

    cudaFuncSetAttribute(mm_f16<MODE_QKV>,   cudaFuncAttributeMaxDynamicSharedMemorySize, GSMEM_BYTES);
    cudaFuncSetAttribute(mm_f16<MODE_LCA>,   cudaFuncAttributeMaxDynamicSharedMemorySize, GSMEM_BYTES);
    cudaFuncSetAttribute(mm_f16<MODE_SCORE>, cudaFuncAttributeMaxDynamicSharedMemorySize, GSMEM_BYTES);
    cudaFuncSetAttribute(mm_f16<MODE_PV>,    cudaFuncAttributeMaxDynamicSharedMemorySize, GSMEM_BYTES);
    cudaFuncSetAttribute(mm_f16<MODE_PLAIN>, cudaFuncAttributeMaxDynamicSharedMemorySize, GSMEM_BYTES);

    __half* ab[2] = { abb, abb + 2 * MD };
    __half* vvv = u3 + 2 * MD;

    const dim3 thr(256);

    // 0) pre-round raw GEMM inputs to fp16 (one launch)
    round_all<<<(unsigned)((MD + 4 * DD) / 1024), thr>>>(x, W_qkv, W_out, xr, wqr, wor);

    // 1) symmetrize + zero-diag both G's (fp16)
    symzero2<<<(unsigned)(2 * DD / 256), thr>>>(Gq_raw, Gk_raw, G2h);

    // 2) QKV projections + fused LCA iteration 1 (z<2 writes vs, a0)
    {
        dim3 g(D_SZ / 128, M_SZ / 128, 3);
        mm_f16<MODE_QKV><<<g, thr, GSMEM_BYTES>>>(xr, wqr, u3, D_SZ, D_SZ, D_SZ, D_SZ, 1.f,
                                                  0, DD, MD, nullptr, vs, ab[0],
                                                  loglam_q, loglam_k);
    }

    // 3) transpose V (fp16)
    {
        dim3 g(T_SZ / 32, D_SZ / 32, B_SZ);
        transpose_bt<<<g, dim3(32, 8)>>>(vvv, vt);
    }

    // 4) LCA iterations 2..3: SPARSE (a nearly empty)
    int cur = 0;
    {
        const unsigned g = (unsigned)(2 * M_SZ / 8);   // warp per row, 8 warps/CTA
        for (int it = 0; it < LCA_SPARSE_ITERS; it++) {
            lca_sparse<<<g, thr>>>(ab[cur], G2h, u3, vs, ab[cur ^ 1], loglam_q, loglam_k);
            cur ^= 1;
        }
    }

    // 5) LCA iterations 4..10: dense fp16 tensor GEMM + prox, q+k merged over z
    {
        dim3 g(D_SZ / 128, M_SZ / 128, 2);
        for (int it = 0; it < LCA_DENSE_ITERS; it++) {
            mm_f16<MODE_LCA><<<g, thr, GSMEM_BYTES>>>(ab[cur], G2h, ab[cur ^ 1],
                                                      D_SZ, D_SZ, D_SZ, D_SZ, 1.f,
                                                      MD, DD, MD, u3, vs, nullptr,
                                                      loglam_q, loglam_k);
            cur ^= 1;
        }
    }
    __half* qf = ab[cur];
    __half* kf = ab[cur] + MD;

    // 6) scores S = q k^T / 32, triangular grid (136 live tiles x batch), fp32 out
    {
        dim3 g(136, 1, B_SZ);
        mm_f16<MODE_SCORE><<<g, thr, GSMEM_BYTES>>>(qf, kf, S, D_SZ, D_SZ, D_SZ, T_SZ, 0.03125f,
                                                    TD, TD, TT, nullptr, nullptr, nullptr,
                                                    nullptr, nullptr);
    }

    // 7) causal softmax: fp32 scores -> fp16 probs (single pass)
    {
        dim3 g(T_SZ, B_SZ);
        softmax_causal<<<g, thr>>>(S, Ph);
    }

    // 8) o = P @ V (NT against Vt, causal K-limit), fp16 out
    {
        dim3 g(D_SZ / 128, T_SZ / 128, B_SZ);
        mm_f16<MODE_PV><<<g, thr, GSMEM_BYTES>>>(Ph, vt, o, T_SZ, T_SZ, T_SZ, D_SZ, 1.f,
                                                 TT, TD, TD, nullptr, nullptr, nullptr,
                                                 nullptr, nullptr);
    }

    // 9) out = o @ W_out^T (fp32 output)
    {
        dim3 g(D_SZ / 128, M_SZ / 128, 1);
        mm_f16<MODE_PLAIN><<<g, thr, GSMEM_BYTES>>>(o, wor, out, D_SZ, D_SZ, D_SZ, D_SZ, 1.f,
                                                    0, 0, 0, nullptr, nullptr, nullptr,
                                                    nullptr, nullptr);
    }
}

// round 15
// speedup vs baseline: 1.3538x; 1.0041x over previous
#include <cuda_runtime.h>
#include <cuda_fp16.h>
#include <cstdint>
#include <math.h>

// ---------------- problem constants ----------------
#define B_SZ 4
#define T_SZ 2048
#define D_SZ 1024
#define M_SZ (B_SZ * T_SZ)
#define MD   ((long)M_SZ * D_SZ)
#define DD   ((long)D_SZ * D_SZ)
#define TT   ((long)T_SZ * T_SZ)
#define TD   ((long)T_SZ * D_SZ)
#define ETA_C 0.1f
#define LCA_SPARSE_ITERS 2
#define LCA_DENSE_ITERS  7

// ---------------- scratch (device globals; no allocation) ----------------
__device__ __half g_u3[3 * M_SZ * D_SZ];     // u_q, u_k, v (fp16)
__device__ __half g_vpt[M_SZ * D_SZ];        // V'^T = W_out·V^T per batch [B][D][T] (fp16)
__device__ float  g_vs[2 * M_SZ * D_SZ];     // LCA v-state (fp32)
__device__ __half g_ab[2][2 * M_SZ * D_SZ];  // LCA codes ping-pong x (q,k) (fp16)
__device__ __half g_G2[2 * D_SZ * D_SZ];     // sym zero-diag Gq,Gk (fp16)
__device__ float  g_S[(size_t)B_SZ * T_SZ * T_SZ];   // scores (fp32)
__device__ __half g_Ph[(size_t)B_SZ * T_SZ * T_SZ];  // probs (fp16)
__device__ __half g_xr[M_SZ * D_SZ];         // x (fp16)
__device__ __half g_wqkvr[3 * D_SZ * D_SZ];  // W_qkv (fp16)
__device__ __half g_woutr[D_SZ * D_SZ];      // W_out (fp16)

// ---------------- helpers ----------------
__device__ __forceinline__ uint32_t smem_u32(const void* p) {
    uint32_t a;
    asm("{ .reg .u64 t; cvta.to.shared.u64 t, %1; cvt.u32.u64 %0, t; }" : "=r"(a) : "l"(p));
    return a;
}
__device__ __forceinline__ void cp_async16(uint32_t dst, const void* src) {
    asm volatile("cp.async.cg.shared.global [%0], [%1], 16;" :: "r"(dst), "l"(src));
}
#define CP_COMMIT() asm volatile("cp.async.commit_group;" ::: "memory")
#define CP_WAIT1()  asm volatile("cp.async.wait_group 1;" ::: "memory")
#define CP_WAIT0()  asm volatile("cp.async.wait_group 0;" ::: "memory")

#define LDSM_X4(r, addr) \
    asm volatile("ldmatrix.sync.aligned.m8n8.x4.shared.b16 {%0,%1,%2,%3}, [%4];" \
                 : "=r"((r)[0]), "=r"((r)[1]), "=r"((r)[2]), "=r"((r)[3]) : "r"(addr))

__device__ __forceinline__ void mma_f16(float* c, const uint32_t* a, const uint32_t* b) {
    asm volatile(
        "mma.sync.aligned.m16n8k16.row.col.f32.f16.f16.f32 "
        "{%0,%1,%2,%3}, {%4,%5,%6,%7}, {%8,%9}, {%0,%1,%2,%3};"
        : "+f"(c[0]), "+f"(c[1]), "+f"(c[2]), "+f"(c[3])
        : "r"(a[0]), "r"(a[1]), "r"(a[2]), "r"(a[3]), "r"(b[0]), "r"(b[1]));
}
__device__ __forceinline__ uint32_t h2pack(float a, float b) {
    __half2 h = __floats2half2_rn(a, b);
    return *reinterpret_cast<uint32_t*>(&h);
}
__device__ __forceinline__ float2 h2unpack(uint32_t u) {
    return __half22float2(*reinterpret_cast<__half2*>(&u));
}

// ---------------- GEMM (NT, fp16 in / fp32 acc): C = alpha * A B^T --------------
// PROVEN R14 config: 128x128 CTA tile, 8 warps of 64x32, 2 CTAs/SM, BK=64,
// ldmatrix.x4 from natural 144B-row layout, 3-stage cp.async, 1 barrier/chunk.
#define MODE_QKV   0   // C=u fp16; for z<2 also vs=eta*u (fp32), a0=soft (fp16)
#define MODE_LCA   1   // fused LCA prox; writes fp16 a
#define MODE_SCORE 2   // triangular-grid decode; writes fp32 S
#define MODE_PV    3   // causal K-limit; writes fp32 (final out = P.V'^T)
#define MODE_VP    4   // full-K; writes fp16 (V'^T = W_out.V^T)

#define BK     64
#define ROWB   144                       // bytes per smem row (128 data + 16 pad)
#define ATILE  (128 * ROWB)              // 18432 B per operand tile
#define STAGE_B (2 * ATILE)              // A + B per stage = 36864 B
#define NSTAGE 3
#define GSMEM_BYTES (NSTAGE * STAGE_B)   // 110592 B (2 CTAs/SM -> 216 KB)

template <int MODE>
__global__ void __launch_bounds__(256, 2)
mm_f16(const __half* __restrict__ A, const __half* __restrict__ Bm, void* __restrict__ Cv,
       int K, int ldA, int ldB, int ldC, float alpha,
       long sA, long sB, long sC,
       const __half* __restrict__ U, float* __restrict__ Vst, __half* __restrict__ Aux,
       const float* __restrict__ llq, const float* __restrict__ llk)
{
    int r0, c0;
    if (MODE == MODE_SCORE) {
        const int t = blockIdx.x;                 // t = by*(by+1)/2 + bx, bx<=by
        int by = (int)((sqrtf(8.f * t + 1.f) - 1.f) * 0.5f);
        while ((by + 1) * (by + 2) / 2 <= t) by++;
        while (by * (by + 1) / 2 > t) by--;
        const int bx = t - by * (by + 1) / 2;
        r0 = by * 128; c0 = bx * 128;
    } else {
        r0 = blockIdx.y * 128;
        c0 = blockIdx.x * 128;
    }

    const long bz = blockIdx.z;
    A  += bz * sA;
    Bm += bz * sB;

    extern __shared__ char smem[];
    const uint32_t sbase = smem_u32(smem);

    const int tid  = threadIdx.x;
    const int lane = tid & 31;
    const int wid  = tid >> 5;
    const int wm   = (wid >> 2) * 64;
    const int wn   = (wid & 3) * 32;
    const int lr   = lane >> 2;         // 0..7
    const int lc   = lane & 3;          // 0..3

    const uint32_t a_lm = (uint32_t)(wm + (lane & 15)) * ROWB + (lane & 16);
    const uint32_t b_lm = (uint32_t)(wn + (lane & 7) + ((lane >> 1) & 8)) * ROWB
                        + ((lane << 1) & 16);

    const int kmax = (MODE == MODE_PV) ? min(K, r0 + 128) : K;
    const int nch  = kmax / BK;          // >= 2 for all uses

    float acc[4][4][4];
#pragma unroll
    for (int i = 0; i < 4; i++)
#pragma unroll
        for (int j = 0; j < 4; j++)
#pragma unroll
            for (int e = 0; e < 4; e++) acc[i][j][e] = 0.f;

    auto issue = [&](int c) {
        const int stg = c % NSTAGE;
        const __half* Ac = A  + (long)r0 * ldA + c * BK;
        const __half* Bc = Bm + (long)c0 * ldB + c * BK;
        const uint32_t ab = sbase + stg * STAGE_B;
        const uint32_t bb = ab + ATILE;
#pragma unroll
        for (int i = 0; i < 4; i++) {
            const int idx = tid + i * 256;       // 1024 16B granules per tile
            const int row = idx >> 3, c8 = idx & 7;
            cp_async16(ab + (uint32_t)(row * ROWB + c8 * 16), Ac + (long)row * ldA + c8 * 8);
            cp_async16(bb + (uint32_t)(row * ROWB + c8 * 16), Bc + (long)row * ldB + c8 * 8);
        }
        CP_COMMIT();
    };

    issue(0);
    issue(1);
    for (int c = 0; c < nch; c++) {
        if (c + 1 < nch) CP_WAIT1(); else CP_WAIT0();
        __syncthreads();                 // group c landed; stage (c-1)%3 free
        if (c + 2 < nch) issue(c + 2);

        const uint32_t sb = sbase + (c % NSTAGE) * STAGE_B;
        const uint32_t Aad = sb + a_lm;
        const uint32_t Bad = sb + ATILE + b_lm;
#pragma unroll
        for (int g = 0; g < 4; g++) {    // four 16-k groups per chunk
            const uint32_t goff = g * 32;
            uint32_t af[4][4], bf[2][4];
#pragma unroll
            for (int mt = 0; mt < 4; mt++)
                LDSM_X4(af[mt], Aad + mt * (16 * ROWB) + goff);
#pragma unroll
            for (int p = 0; p < 2; p++)
                LDSM_X4(bf[p], Bad + p * (16 * ROWB) + goff);
#pragma unroll
            for (int mt = 0; mt < 4; mt++)
#pragma unroll
                for (int nt = 0; nt < 4; nt++)
                    mma_f16(acc[mt][nt], af[mt], &bf[nt >> 1][(nt & 1) * 2]);
        }
    }

    // ---------------- epilogue ----------------
    float lam = 0.f;
    if (MODE == MODE_LCA || (MODE == MODE_QKV && bz < 2))
        lam = expf(bz == 0 ? *llq : *llk);
#pragma unroll
    for (int mt = 0; mt < 4; mt++) {
#pragma unroll
        for (int h = 0; h < 2; h++) {
            const int row = r0 + wm + mt * 16 + lr + h * 8;
#pragma unroll
            for (int nt = 0; nt < 4; nt++) {
                const int col = c0 + wn + nt * 8 + lc * 2;
                const long idx = (long)row * ldC + col;
                float x0 = acc[mt][nt][h * 2 + 0];
                float x1 = acc[mt][nt][h * 2 + 1];
                if (MODE == MODE_LCA) {
                    __half* Ch = (__half*)Cv + bz * sC;
                    float2 u2 = h2unpack(*(const uint32_t*)(U + bz * sC + idx));
                    float2 v2 = *(const float2*)(Vst + bz * sC + idx);
                    float2 vn;
                    vn.x = v2.x + ETA_C * (u2.x - v2.x - x0);
                    vn.y = v2.y + ETA_C * (u2.y - v2.y - x1);
                    *(float2*)(Vst + bz * sC + idx) = vn;
                    float s, o0, o1;
                    s = fabsf(vn.x) - lam; o0 = (s > 0.f) ? copysignf(s, vn.x) : 0.f;
                    s = fabsf(vn.y) - lam; o1 = (s > 0.f) ? copysignf(s, vn.y) : 0.f;
                    *(uint32_t*)(Ch + idx) = h2pack(o0, o1);
                } else if (MODE == MODE_QKV) {
                    __half* Ch = (__half*)Cv + bz * sC;
                    *(uint32_t*)(Ch + idx) = h2pack(x0, x1);         // u (fp16)
                    if (bz < 2) {                                    // fused LCA iter 1
                        float2 vn = make_float2(ETA_C * x0, ETA_C * x1);
                        *(float2*)(Vst + bz * sC + idx) = vn;
                        float s, o0, o1;
                        s = fabsf(vn.x) - lam; o0 = (s > 0.f) ? copysignf(s, vn.x) : 0.f;
                        s = fabsf(vn.y) - lam; o1 = (s > 0.f) ? copysignf(s, vn.y) : 0.f;
                        *(uint32_t*)(Aux + bz * sC + idx) = h2pack(o0, o1);
                    }
                } else if (MODE == MODE_VP) {
                    __half* Ch = (__half*)Cv + bz * sC;
                    *(uint32_t*)(Ch + idx) = h2pack(x0, x1);         // V'^T (fp16)
                } else {  // SCORE / PV -> fp32
                    float* Cf = (float*)Cv + bz * sC;
                    *(float2*)(Cf + idx) = make_float2(alpha * x0, alpha * x1);
                }
            }
        }
    }
}

// ---------------- sparse LCA iteration: warp per row (fp16 a/G/u) -------------
__global__ void __launch_bounds__(256, 4)
lca_sparse(const __half* __restrict__ a_in, const __half* __restrict__ G2,
           const __half* __restrict__ U, float* __restrict__ Vst,
           __half* __restrict__ a_out,
           const float* __restrict__ llq, const float* __restrict__ llk)
{
    const long row  = ((long)blockIdx.x * blockDim.x + threadIdx.x) >> 5;
    const int  lane = threadIdx.x & 31;
    const int  half = (row >= M_SZ);
    const __half* G = G2 + (long)half * DD;
    const float lam = expf(half ? *llk : *llq);

    const __half* arow = a_in + row * D_SZ;

    float acc[8][4];
#pragma unroll
    for (int j = 0; j < 8; j++)
#pragma unroll
        for (int i = 0; i < 4; i++) acc[j][i] = 0.f;

#pragma unroll
    for (int j = 0; j < 8; j++) {
        const __half2* ap = (const __half2*)(arow + lane * 4 + 128 * j);
        const float2 f0 = __half22float2(ap[0]);
        const float2 f1 = __half22float2(ap[1]);
        const float vals[4] = { f0.x, f0.y, f1.x, f1.y };
#pragma unroll
        for (int i = 0; i < 4; i++) {
            unsigned m = __ballot_sync(0xFFFFFFFFu, vals[i] != 0.f);
            while (m) {
                const int s = __ffs(m) - 1;
                m &= m - 1;
                const float aval = __shfl_sync(0xFFFFFFFFu, vals[i], s);
                const int k = s * 4 + 128 * j + i;
                const __half* Gr = G + (long)k * D_SZ + lane * 4;
#pragma unroll
                for (int jj = 0; jj < 8; jj++) {
                    const __half2* gp = (const __half2*)(Gr + 128 * jj);
                    const float2 g0 = __half22float2(gp[0]);
                    const float2 g1 = __half22float2(gp[1]);
                    acc[jj][0] += aval * g0.x;
                    acc[jj][1] += aval * g0.y;
                    acc[jj][2] += aval * g1.x;
                    acc[jj][3] += aval * g1.y;
                }
            }
        }
    }

    const __half* urow = U + row * D_SZ;
    float* vrow = Vst + row * D_SZ;
    __half* orow = a_out + row * D_SZ;
#pragma unroll
    for (int j = 0; j < 8; j++) {
        const int c = lane * 4 + 128 * j;
        const __half2* up = (const __half2*)(urow + c);
        const float2 u0 = __half22float2(up[0]);
        const float2 u1 = __half22float2(up[1]);
        const float4 vv = *(const float4*)(vrow + c);
        float4 vn;
        vn.x = vv.x + ETA_C * (u0.x - vv.x - acc[j][0]);
        vn.y = vv.y + ETA_C * (u0.y - vv.y - acc[j][1]);
        vn.z = vv.z + ETA_C * (u1.x - vv.z - acc[j][2]);
        vn.w = vv.w + ETA_C * (u1.y - vv.w - acc[j][3]);
        *(float4*)(vrow + c) = vn;
        float s, o0, o1, o2, o3;
        s = fabsf(vn.x) - lam; o0 = (s > 0.f) ? copysignf(s, vn.x) : 0.f;
        s = fabsf(vn.y) - lam; o1 = (s > 0.f) ? copysignf(s, vn.y) : 0.f;
        s = fabsf(vn.z) - lam; o2 = (s > 0.f) ? copysignf(s, vn.z) : 0.f;
        s = fabsf(vn.w) - lam; o3 = (s > 0.f) ? copysignf(s, vn.w) : 0.f;
        uint2 pk = make_uint2(h2pack(o0, o1), h2pack(o2, o3));
        *(uint2*)(orow + c) = pk;
    }
}

// ---------------- small kernels ----------------
__global__ void round_all(const float* __restrict__ x, const float* __restrict__ wq,
                          const float* __restrict__ wo,
                          __half* __restrict__ xr, __half* __restrict__ wqr,
                          __half* __restrict__ wor)
{
    const long i = ((long)blockIdx.x * blockDim.x + threadIdx.x) * 4;
    const float* in; __half* out; long off;
    if (i < MD)               { in = x;  out = xr;  off = i; }
    else if (i < MD + 3 * DD) { in = wq; out = wqr; off = i - MD; }
    else                      { in = wo; out = wor; off = i - MD - 3 * DD; }
    float4 v = *(const float4*)(in + off);
    uint2 pk = make_uint2(h2pack(v.x, v.y), h2pack(v.z, v.w));
    *(uint2*)(out + off) = pk;
}

__global__ void symzero2(const float* __restrict__ Gq, const float* __restrict__ Gk,
                         __half* __restrict__ Gs)
{
    const long idx = (long)blockIdx.x * blockDim.x + threadIdx.x;
    const long e = idx & (DD - 1);
    const float* G = (idx < DD) ? Gq : Gk;
    const int i = (int)(e / D_SZ), j = (int)(e % D_SZ);
    Gs[idx] = (i == j) ? __float2half_rn(0.f)
                       : __float2half_rn(0.5f * (G[e] + G[(long)j * D_SZ + i]));
}

// single-pass causal softmax: read S once, keep exp in regs, write fp16 probs once
__global__ void softmax_causal(const float* __restrict__ S, __half* __restrict__ Ph)
{
    const int i = blockIdx.x;
    const int b = blockIdx.y;
    const float* row = S + ((long)b * T_SZ + i) * T_SZ;
    __half* prow = Ph + ((long)b * T_SZ + i) * T_SZ;
    const int tid = threadIdx.x;
    const int n = i + 1;
    __shared__ float red[256];

    float v[8];
    int cnt = 0;
    float mx = -INFINITY;
    for (int j = tid; j < n; j += 256) { v[cnt++] = row[j]; mx = fmaxf(mx, v[cnt - 1]); }

    red[tid] = mx;
    __syncthreads();
    for (int s = 128; s > 0; s >>= 1) {
        if (tid < s) red[tid] = fmaxf(red[tid], red[tid + s]);
        __syncthreads();
    }
    mx = red[0];
    __syncthreads();

    float sum = 0.f;
#pragma unroll
    for (int c = 0; c < 8; c++)
        if (c < cnt) { v[c] = expf(v[c] - mx); sum += v[c]; }
    red[tid] = sum;
    __syncthreads();
    for (int s = 128; s > 0; s >>= 1) {
        if (tid < s) red[tid] += red[tid + s];
        __syncthreads();
    }
    const float inv = 1.f / red[0];

    int c = 0;
    for (int j = tid; j < n; j += 256) prow[j] = __float2half_rn(v[c++] * inv);
    for (int j = n + tid; j < T_SZ; j += 256) prow[j] = __float2half_rn(0.f);
}

// ---------------- launch ----------------
extern "C" void kernel_launch(void* const* d_in, const int* in_sizes, int n_in,
                              void* d_out, int out_size)
{
    const float* x        = (const float*)d_in[0];
    const float* W_qkv    = (const float*)d_in[1];
    const float* W_out    = (const float*)d_in[2];
    const float* Gq_raw   = (const float*)d_in[3];
    const float* loglam_q = (const float*)d_in[4];
    const float* Gk_raw   = (const float*)d_in[5];
    const float* loglam_k = (const float*)d_in[6];
    float* out = (float*)d_out;
    (void)in_sizes; (void)n_in; (void)out_size;

    float *vs, *S;
    __half *u3, *vpt, *abb, *G2h, *Ph, *xr, *wqr, *wor;
    cudaGetSymbolAddress((void**)&u3,  g_u3);
    cudaGetSymbolAddress((void**)&vpt, g_vpt);
    cudaGetSymbolAddress((void**)&vs,  g_vs);
    cudaGetSymbolAddress((void**)&abb, g_ab);
    cudaGetSymbolAddress((void**)&G2h, g_G2);
    cudaGetSymbolAddress((void**)&S,   g_S);
    cudaGetSymbolAddress((void**)&Ph,  g_Ph);
    cudaGetSymbolAddress((void**)&xr,  g_xr);
    cudaGetSymbolAddress((void**)&wqr, g_wqkvr);
    cudaGetSymbolAddress((void**)&wor, g_woutr);

    cudaFuncSetAttribute(mm_f16<MODE_QKV>,   cudaFuncAttributeMaxDynamicSharedMemorySize, GSMEM_BYTES);
    cudaFuncSetAttribute(mm_f16<MODE_LCA>,   cudaFuncAttributeMaxDynamicSharedMemorySize, GSMEM_BYTES);
    cudaFuncSetAttribute(mm_f16<MODE_SCORE>, cudaFuncAttributeMaxDynamicSharedMemorySize, GSMEM_BYTES);
    cudaFuncSetAttribute(mm_f16<MODE_PV>,    cudaFuncAttributeMaxDynamicSharedMemorySize, GSMEM_BYTES);
    cudaFuncSetAttribute(mm_f16<MODE_VP>,    cudaFuncAttributeMaxDynamicSharedMemorySize, GSMEM_BYTES);

    __half* ab[2] = { abb, abb + 2 * MD };
    __half* vvv = u3 + 2 * MD;

    const dim3 thr(256);

    // 0) pre-round raw GEMM inputs to fp16 (one launch)
    round_all<<<(unsigned)((MD + 4 * DD) / 1024), thr>>>(x, W_qkv, W_out, xr, wqr, wor);

    // 1) symmetrize + zero-diag both G's (fp16)
    symzero2<<<(unsigned)(2 * DD / 256), thr>>>(Gq_raw, Gk_raw, G2h);

    // 2) QKV projections + fused LCA iteration 1 (z<2 writes vs, a0)
    {
        dim3 g(D_SZ / 128, M_SZ / 128, 3);
        mm_f16<MODE_QKV><<<g, thr, GSMEM_BYTES>>>(xr, wqr, u3, D_SZ, D_SZ, D_SZ, D_SZ, 1.f,
                                                  0, DD, MD, nullptr, vs, ab[0],
                                                  loglam_q, loglam_k);
    }

    // 3) V'^T = W_out . V^T (NT: A=W_out [D,D], B=V [T,D] per batch) -> [B][D][T] fp16
    {
        dim3 g(T_SZ / 128, D_SZ / 128, B_SZ);
        mm_f16<MODE_VP><<<g, thr, GSMEM_BYTES>>>(wor, vvv, vpt, D_SZ, D_SZ, D_SZ, T_SZ, 1.f,
                                                 0, TD, TD, nullptr, nullptr, nullptr,
                                                 nullptr, nullptr);
    }

    // 4) LCA iterations 2..3: SPARSE (a nearly empty)
    int cur = 0;
    {
        const unsigned g = (unsigned)(2 * M_SZ / 8);   // warp per row, 8 warps/CTA
        for (int it = 0; it < LCA_SPARSE_ITERS; it++) {
            lca_sparse<<<g, thr>>>(ab[cur], G2h, u3, vs, ab[cur ^ 1], loglam_q, loglam_k);
            cur ^= 1;
        }
    }

    // 5) LCA iterations 4..10: dense fp16 tensor GEMM + prox, q+k merged over z
    {
        dim3 g(D_SZ / 128, M_SZ / 128, 2);
        for (int it = 0; it < LCA_DENSE_ITERS; it++) {
            mm_f16<MODE_LCA><<<g, thr, GSMEM_BYTES>>>(ab[cur], G2h, ab[cur ^ 1],
                                                      D_SZ, D_SZ, D_SZ, D_SZ, 1.f,
                                                      MD, DD, MD, u3, vs, nullptr,
                                                      loglam_q, loglam_k);
            cur ^= 1;
        }
    }
    __half* qf = ab[cur];
    __half* kf = ab[cur] + MD;

    // 6) scores S = q k^T / 32, triangular grid (136 live tiles x batch), fp32 out
    {
        dim3 g(136, 1, B_SZ);
        mm_f16<MODE_SCORE><<<g, thr, GSMEM_BYTES>>>(qf, kf, S, D_SZ, D_SZ, D_SZ, T_SZ, 0.03125f,
                                                    TD, TD, TT, nullptr, nullptr, nullptr,
                                                    nullptr, nullptr);
    }

    // 7) causal softmax: fp32 scores -> fp16 probs (single pass)
    {
        dim3 g(T_SZ, B_SZ);
        softmax_causal<<<g, thr>>>(S, Ph);
    }

    // 8) out = P . V'^T (NT, causal K-limit), fp32 straight to output
    {
        dim3 g(D_SZ / 128, T_SZ / 128, B_SZ);
        mm_f16<MODE_PV><<<g, thr, GSMEM_BYTES>>>(Ph, vpt, out, T_SZ, T_SZ, T_SZ, D_SZ, 1.f,
                                                 TT, TD, TD, nullptr, nullptr, nullptr,
                                                 nullptr, nullptr);
    }
}

// round 16
// speedup vs baseline: 1.3652x; 1.0085x over previous
#include <cuda_runtime.h>
#include <cuda_fp16.h>
#include <cstdint>
#include <math.h>

// ---------------- problem constants ----------------
#define B_SZ 4
#define T_SZ 2048
#define D_SZ 1024
#define M_SZ (B_SZ * T_SZ)
#define MD   ((long)M_SZ * D_SZ)
#define DD   ((long)D_SZ * D_SZ)
#define TT   ((long)T_SZ * T_SZ)
#define TD   ((long)T_SZ * D_SZ)
#define ETA_C 0.1f
#define LCA_SPARSE_ITERS 2
#define LCA_DENSE_ITERS  7

// ---------------- scratch (device globals; no allocation) ----------------
__device__ __half g_u3[3 * M_SZ * D_SZ];     // u_q, u_k, v (fp16)
__device__ __half g_vpt[M_SZ * D_SZ];        // V'^T = W_out·V^T per batch [B][D][T] (fp16)
__device__ float  g_vs[2 * M_SZ * D_SZ];     // LCA v-state (fp32)
__device__ __half g_ab[2][2 * M_SZ * D_SZ];  // LCA codes ping-pong x (q,k) (fp16)
__device__ __half g_G2[2 * D_SZ * D_SZ];     // sym zero-diag Gq,Gk (fp16)
__device__ float  g_S[(size_t)B_SZ * T_SZ * T_SZ];   // scores (fp32)
__device__ __half g_Ph[(size_t)B_SZ * T_SZ * T_SZ];  // probs (fp16)
__device__ __half g_xr[M_SZ * D_SZ];         // x (fp16)
__device__ __half g_wqkvr[3 * D_SZ * D_SZ];  // W_qkv (fp16)
__device__ __half g_woutr[D_SZ * D_SZ];      // W_out (fp16)

// ---------------- helpers ----------------
__device__ __forceinline__ uint32_t smem_u32(const void* p) {
    uint32_t a;
    asm("{ .reg .u64 t; cvta.to.shared.u64 t, %1; cvt.u32.u64 %0, t; }" : "=r"(a) : "l"(p));
    return a;
}
__device__ __forceinline__ void cp_async16(uint32_t dst, const void* src) {
    asm volatile("cp.async.cg.shared.global [%0], [%1], 16;" :: "r"(dst), "l"(src));
}
#define CP_COMMIT() asm volatile("cp.async.commit_group;" ::: "memory")
#define CP_WAIT1()  asm volatile("cp.async.wait_group 1;" ::: "memory")
#define CP_WAIT0()  asm volatile("cp.async.wait_group 0;" ::: "memory")

#define LDSM_X4(r, addr) \
    asm volatile("ldmatrix.sync.aligned.m8n8.x4.shared.b16 {%0,%1,%2,%3}, [%4];" \
                 : "=r"((r)[0]), "=r"((r)[1]), "=r"((r)[2]), "=r"((r)[3]) : "r"(addr))

__device__ __forceinline__ void mma_f16(float* c, const uint32_t* a, const uint32_t* b) {
    asm volatile(
        "mma.sync.aligned.m16n8k16.row.col.f32.f16.f16.f32 "
        "{%0,%1,%2,%3}, {%4,%5,%6,%7}, {%8,%9}, {%0,%1,%2,%3};"
        : "+f"(c[0]), "+f"(c[1]), "+f"(c[2]), "+f"(c[3])
        : "r"(a[0]), "r"(a[1]), "r"(a[2]), "r"(a[3]), "r"(b[0]), "r"(b[1]));
}
__device__ __forceinline__ uint32_t h2pack(float a, float b) {
    __half2 h = __floats2half2_rn(a, b);
    return *reinterpret_cast<uint32_t*>(&h);
}
__device__ __forceinline__ float2 h2unpack(uint32_t u) {
    return __half22float2(*reinterpret_cast<__half2*>(&u));
}

// ---------------- GEMM (NT, fp16 in / fp32 acc): C = alpha * A B^T --------------
// PROVEN R14 config: 128x128 CTA tile, 8 warps of 64x32, 2 CTAs/SM, BK=64,
// ldmatrix.x4 from natural 144B-row layout, 3-stage cp.async, 1 barrier/chunk.
#define MODE_QKV   0   // C=u fp16; for z<2 also vs=eta*u (fp32), a0=soft (fp16)
#define MODE_LCA   1   // fused LCA prox; writes fp16 a
#define MODE_SCORE 2   // triangular-grid decode; writes fp32 S
#define MODE_PV    3   // causal K-limit; writes fp32 (final out = P.V'^T)
#define MODE_VP    4   // full-K; writes fp16 (V'^T = W_out.V^T)

#define BK     64
#define ROWB   144                       // bytes per smem row (128 data + 16 pad)
#define ATILE  (128 * ROWB)              // 18432 B per operand tile
#define STAGE_B (2 * ATILE)              // A + B per stage = 36864 B
#define NSTAGE 3
#define GSMEM_BYTES (NSTAGE * STAGE_B)   // 110592 B (2 CTAs/SM -> 216 KB)

template <int MODE>
__global__ void __launch_bounds__(256, 2)
mm_f16(const __half* __restrict__ A, const __half* __restrict__ Bm, void* __restrict__ Cv,
       int K, int ldA, int ldB, int ldC, float alpha,
       long sA, long sB, long sC,
       const __half* __restrict__ U, float* __restrict__ Vst, __half* __restrict__ Aux,
       const float* __restrict__ llq, const float* __restrict__ llk)
{
    int r0, c0;
    if (MODE == MODE_SCORE) {
        const int t = blockIdx.x;                 // t = by*(by+1)/2 + bx, bx<=by
        int by = (int)((sqrtf(8.f * t + 1.f) - 1.f) * 0.5f);
        while ((by + 1) * (by + 2) / 2 <= t) by++;
        while (by * (by + 1) / 2 > t) by--;
        const int bx = t - by * (by + 1) / 2;
        r0 = by * 128; c0 = bx * 128;
    } else {
        r0 = blockIdx.y * 128;
        c0 = blockIdx.x * 128;
    }

    const long bz = blockIdx.z;
    A  += bz * sA;
    Bm += bz * sB;

    extern __shared__ char smem[];
    const uint32_t sbase = smem_u32(smem);

    const int tid  = threadIdx.x;
    const int lane = tid & 31;
    const int wid  = tid >> 5;
    const int wm   = (wid >> 2) * 64;
    const int wn   = (wid & 3) * 32;
    const int lr   = lane >> 2;         // 0..7
    const int lc   = lane & 3;          // 0..3

    const uint32_t a_lm = (uint32_t)(wm + (lane & 15)) * ROWB + (lane & 16);
    const uint32_t b_lm = (uint32_t)(wn + (lane & 7) + ((lane >> 1) & 8)) * ROWB
                        + ((lane << 1) & 16);

    const int kmax = (MODE == MODE_PV) ? min(K, r0 + 128) : K;
    const int nch  = kmax / BK;          // >= 2 for all uses

    float acc[4][4][4];
#pragma unroll
    for (int i = 0; i < 4; i++)
#pragma unroll
        for (int j = 0; j < 4; j++)
#pragma unroll
            for (int e = 0; e < 4; e++) acc[i][j][e] = 0.f;

    auto issue = [&](int c) {
        const int stg = c % NSTAGE;
        const __half* Ac = A  + (long)r0 * ldA + c * BK;
        const __half* Bc = Bm + (long)c0 * ldB + c * BK;
        const uint32_t ab = sbase + stg * STAGE_B;
        const uint32_t bb = ab + ATILE;
#pragma unroll
        for (int i = 0; i < 4; i++) {
            const int idx = tid + i * 256;       // 1024 16B granules per tile
            const int row = idx >> 3, c8 = idx & 7;
            cp_async16(ab + (uint32_t)(row * ROWB + c8 * 16), Ac + (long)row * ldA + c8 * 8);
            cp_async16(bb + (uint32_t)(row * ROWB + c8 * 16), Bc + (long)row * ldB + c8 * 8);
        }
        CP_COMMIT();
    };

    issue(0);
    issue(1);
    for (int c = 0; c < nch; c++) {
        if (c + 1 < nch) CP_WAIT1(); else CP_WAIT0();
        __syncthreads();                 // group c landed; stage (c-1)%3 free
        if (c + 2 < nch) issue(c + 2);

        const uint32_t sb = sbase + (c % NSTAGE) * STAGE_B;
        const uint32_t Aad = sb + a_lm;
        const uint32_t Bad = sb + ATILE + b_lm;
#pragma unroll
        for (int g = 0; g < 4; g++) {    // four 16-k groups per chunk
            const uint32_t goff = g * 32;
            uint32_t af[4][4], bf[2][4];
#pragma unroll
            for (int mt = 0; mt < 4; mt++)
                LDSM_X4(af[mt], Aad + mt * (16 * ROWB) + goff);
#pragma unroll
            for (int p = 0; p < 2; p++)
                LDSM_X4(bf[p], Bad + p * (16 * ROWB) + goff);
#pragma unroll
            for (int mt = 0; mt < 4; mt++)
#pragma unroll
                for (int nt = 0; nt < 4; nt++)
                    mma_f16(acc[mt][nt], af[mt], &bf[nt >> 1][(nt & 1) * 2]);
        }
    }

    // ---------------- epilogue ----------------
    float lam = 0.f;
    if (MODE == MODE_LCA || (MODE == MODE_QKV && bz < 2))
        lam = expf(bz == 0 ? *llq : *llk);
#pragma unroll
    for (int mt = 0; mt < 4; mt++) {
#pragma unroll
        for (int h = 0; h < 2; h++) {
            const int row = r0 + wm + mt * 16 + lr + h * 8;
#pragma unroll
            for (int nt = 0; nt < 4; nt++) {
                const int col = c0 + wn + nt * 8 + lc * 2;
                const long idx = (long)row * ldC + col;
                float x0 = acc[mt][nt][h * 2 + 0];
                float x1 = acc[mt][nt][h * 2 + 1];
                if (MODE == MODE_LCA) {
                    __half* Ch = (__half*)Cv + bz * sC;
                    float2 u2 = h2unpack(*(const uint32_t*)(U + bz * sC + idx));
                    float2 v2 = *(const float2*)(Vst + bz * sC + idx);
                    float2 vn;
                    vn.x = v2.x + ETA_C * (u2.x - v2.x - x0);
                    vn.y = v2.y + ETA_C * (u2.y - v2.y - x1);
                    *(float2*)(Vst + bz * sC + idx) = vn;
                    float s, o0, o1;
                    s = fabsf(vn.x) - lam; o0 = (s > 0.f) ? copysignf(s, vn.x) : 0.f;
                    s = fabsf(vn.y) - lam; o1 = (s > 0.f) ? copysignf(s, vn.y) : 0.f;
                    *(uint32_t*)(Ch + idx) = h2pack(o0, o1);
                } else if (MODE == MODE_QKV) {
                    __half* Ch = (__half*)Cv + bz * sC;
                    *(uint32_t*)(Ch + idx) = h2pack(x0, x1);         // u (fp16)
                    if (bz < 2) {                                    // fused LCA iter 1
                        float2 vn = make_float2(ETA_C * x0, ETA_C * x1);
                        *(float2*)(Vst + bz * sC + idx) = vn;
                        float s, o0, o1;
                        s = fabsf(vn.x) - lam; o0 = (s > 0.f) ? copysignf(s, vn.x) : 0.f;
                        s = fabsf(vn.y) - lam; o1 = (s > 0.f) ? copysignf(s, vn.y) : 0.f;
                        *(uint32_t*)(Aux + bz * sC + idx) = h2pack(o0, o1);
                    }
                } else if (MODE == MODE_VP) {
                    __half* Ch = (__half*)Cv + bz * sC;
                    *(uint32_t*)(Ch + idx) = h2pack(x0, x1);         // V'^T (fp16)
                } else {  // SCORE / PV -> fp32
                    float* Cf = (float*)Cv + bz * sC;
                    *(float2*)(Cf + idx) = make_float2(alpha * x0, alpha * x1);
                }
            }
        }
    }
}

// ---------------- sparse LCA iteration: warp per row (fp16 a/G/u) -------------
__global__ void __launch_bounds__(256, 4)
lca_sparse(const __half* __restrict__ a_in, const __half* __restrict__ G2,
           const __half* __restrict__ U, float* __restrict__ Vst,
           __half* __restrict__ a_out,
           const float* __restrict__ llq, const float* __restrict__ llk)
{
    const long row  = ((long)blockIdx.x * blockDim.x + threadIdx.x) >> 5;
    const int  lane = threadIdx.x & 31;
    const int  half = (row >= M_SZ);
    const __half* G = G2 + (long)half * DD;
    const float lam = expf(half ? *llk : *llq);

    const __half* arow = a_in + row * D_SZ;

    float acc[8][4];
#pragma unroll
    for (int j = 0; j < 8; j++)
#pragma unroll
        for (int i = 0; i < 4; i++) acc[j][i] = 0.f;

#pragma unroll
    for (int j = 0; j < 8; j++) {
        const __half2* ap = (const __half2*)(arow + lane * 4 + 128 * j);
        const float2 f0 = __half22float2(ap[0]);
        const float2 f1 = __half22float2(ap[1]);
        const float vals[4] = { f0.x, f0.y, f1.x, f1.y };
#pragma unroll
        for (int i = 0; i < 4; i++) {
            unsigned m = __ballot_sync(0xFFFFFFFFu, vals[i] != 0.f);
            while (m) {
                const int s = __ffs(m) - 1;
                m &= m - 1;
                const float aval = __shfl_sync(0xFFFFFFFFu, vals[i], s);
                const int k = s * 4 + 128 * j + i;
                const __half* Gr = G + (long)k * D_SZ + lane * 4;
#pragma unroll
                for (int jj = 0; jj < 8; jj++) {
                    const __half2* gp = (const __half2*)(Gr + 128 * jj);
                    const float2 g0 = __half22float2(gp[0]);
                    const float2 g1 = __half22float2(gp[1]);
                    acc[jj][0] += aval * g0.x;
                    acc[jj][1] += aval * g0.y;
                    acc[jj][2] += aval * g1.x;
                    acc[jj][3] += aval * g1.y;
                }
            }
        }
    }

    const __half* urow = U + row * D_SZ;
    float* vrow = Vst + row * D_SZ;
    __half* orow = a_out + row * D_SZ;
#pragma unroll
    for (int j = 0; j < 8; j++) {
        const int c = lane * 4 + 128 * j;
        const __half2* up = (const __half2*)(urow + c);
        const float2 u0 = __half22float2(up[0]);
        const float2 u1 = __half22float2(up[1]);
        const float4 vv = *(const float4*)(vrow + c);
        float4 vn;
        vn.x = vv.x + ETA_C * (u0.x - vv.x - acc[j][0]);
        vn.y = vv.y + ETA_C * (u0.y - vv.y - acc[j][1]);
        vn.z = vv.z + ETA_C * (u1.x - vv.z - acc[j][2]);
        vn.w = vv.w + ETA_C * (u1.y - vv.w - acc[j][3]);
        *(float4*)(vrow + c) = vn;
        float s, o0, o1, o2, o3;
        s = fabsf(vn.x) - lam; o0 = (s > 0.f) ? copysignf(s, vn.x) : 0.f;
        s = fabsf(vn.y) - lam; o1 = (s > 0.f) ? copysignf(s, vn.y) : 0.f;
        s = fabsf(vn.z) - lam; o2 = (s > 0.f) ? copysignf(s, vn.z) : 0.f;
        s = fabsf(vn.w) - lam; o3 = (s > 0.f) ? copysignf(s, vn.w) : 0.f;
        uint2 pk = make_uint2(h2pack(o0, o1), h2pack(o2, o3));
        *(uint2*)(orow + c) = pk;
    }
}

// ---------------- small kernels ----------------
__global__ void round_all(const float* __restrict__ x, const float* __restrict__ wq,
                          const float* __restrict__ wo,
                          __half* __restrict__ xr, __half* __restrict__ wqr,
                          __half* __restrict__ wor)
{
    const long i = ((long)blockIdx.x * blockDim.x + threadIdx.x) * 4;
    const float* in; __half* out; long off;
    if (i < MD)               { in = x;  out = xr;  off = i; }
    else if (i < MD + 3 * DD) { in = wq; out = wqr; off = i - MD; }
    else                      { in = wo; out = wor; off = i - MD - 3 * DD; }
    float4 v = *(const float4*)(in + off);
    uint2 pk = make_uint2(h2pack(v.x, v.y), h2pack(v.z, v.w));
    *(uint2*)(out + off) = pk;
}

__global__ void symzero2(const float* __restrict__ Gq, const float* __restrict__ Gk,
                         __half* __restrict__ Gs)
{
    const long idx = (long)blockIdx.x * blockDim.x + threadIdx.x;
    const long e = idx & (DD - 1);
    const float* G = (idx < DD) ? Gq : Gk;
    const int i = (int)(e / D_SZ), j = (int)(e % D_SZ);
    Gs[idx] = (i == j) ? __float2half_rn(0.f)
                       : __float2half_rn(0.5f * (G[e] + G[(long)j * D_SZ + i]));
}

// single-pass causal softmax: read S once, keep exp in regs, write fp16 probs once
__global__ void softmax_causal(const float* __restrict__ S, __half* __restrict__ Ph)
{
    const int i = blockIdx.x;
    const int b = blockIdx.y;
    const float* row = S + ((long)b * T_SZ + i) * T_SZ;
    __half* prow = Ph + ((long)b * T_SZ + i) * T_SZ;
    const int tid = threadIdx.x;
    const int n = i + 1;
    __shared__ float red[256];

    float v[8];
    int cnt = 0;
    float mx = -INFINITY;
    for (int j = tid; j < n; j += 256) { v[cnt++] = row[j]; mx = fmaxf(mx, v[cnt - 1]); }

    red[tid] = mx;
    __syncthreads();
    for (int s = 128; s > 0; s >>= 1) {
        if (tid < s) red[tid] = fmaxf(red[tid], red[tid + s]);
        __syncthreads();
    }
    mx = red[0];
    __syncthreads();

    float sum = 0.f;
#pragma unroll
    for (int c = 0; c < 8; c++)
        if (c < cnt) { v[c] = expf(v[c] - mx); sum += v[c]; }
    red[tid] = sum;
    __syncthreads();
    for (int s = 128; s > 0; s >>= 1) {
        if (tid < s) red[tid] += red[tid + s];
        __syncthreads();
    }
    const float inv = 1.f / red[0];

    int c = 0;
    for (int j = tid; j < n; j += 256) prow[j] = __float2half_rn(v[c++] * inv);
    for (int j = n + tid; j < T_SZ; j += 256) prow[j] = __float2half_rn(0.f);
}

// ---------------- launch ----------------
extern "C" void kernel_launch(void* const* d_in, const int* in_sizes, int n_in,
                              void* d_out, int out_size)
{
    const float* x        = (const float*)d_in[0];
    const float* W_qkv    = (const float*)d_in[1];
    const float* W_out    = (const float*)d_in[2];
    const float* Gq_raw   = (const float*)d_in[3];
    const float* loglam_q = (const float*)d_in[4];
    const float* Gk_raw   = (const float*)d_in[5];
    const float* loglam_k = (const float*)d_in[6];
    float* out = (float*)d_out;
    (void)in_sizes; (void)n_in; (void)out_size;

    float *vs, *S;
    __half *u3, *vpt, *abb, *G2h, *Ph, *xr, *wqr, *wor;
    cudaGetSymbolAddress((void**)&u3,  g_u3);
    cudaGetSymbolAddress((void**)&vpt, g_vpt);
    cudaGetSymbolAddress((void**)&vs,  g_vs);
    cudaGetSymbolAddress((void**)&abb, g_ab);
    cudaGetSymbolAddress((void**)&G2h, g_G2);
    cudaGetSymbolAddress((void**)&S,   g_S);
    cudaGetSymbolAddress((void**)&Ph,  g_Ph);
    cudaGetSymbolAddress((void**)&xr,  g_xr);
    cudaGetSymbolAddress((void**)&wqr, g_wqkvr);
    cudaGetSymbolAddress((void**)&wor, g_woutr);

    cudaFuncSetAttribute(mm_f16<MODE_QKV>,   cudaFuncAttributeMaxDynamicSharedMemorySize, GSMEM_BYTES);
    cudaFuncSetAttribute(mm_f16<MODE_LCA>,   cudaFuncAttributeMaxDynamicSharedMemorySize, GSMEM_BYTES);
    cudaFuncSetAttribute(mm_f16<MODE_SCORE>, cudaFuncAttributeMaxDynamicSharedMemorySize, GSMEM_BYTES);
    cudaFuncSetAttribute(mm_f16<MODE_PV>,    cudaFuncAttributeMaxDynamicSharedMemorySize, GSMEM_BYTES);
    cudaFuncSetAttribute(mm_f16<MODE_VP>,    cudaFuncAttributeMaxDynamicSharedMemorySize, GSMEM_BYTES);

    // one-time stream/event infrastructure (host-side; identical work per call)
    static cudaStream_t s2 = nullptr;
    static cudaEvent_t evFork = nullptr, evJoin = nullptr;
    if (s2 == nullptr) {
        cudaStreamCreateWithFlags(&s2, cudaStreamNonBlocking);
        cudaEventCreateWithFlags(&evFork, cudaEventDisableTiming);
        cudaEventCreateWithFlags(&evJoin, cudaEventDisableTiming);
    }

    __half* ab[2] = { abb, abb + 2 * MD };
    __half* vvv = u3 + 2 * MD;

    const dim3 thr(256);

    // 0) pre-round raw GEMM inputs to fp16 (one launch)
    round_all<<<(unsigned)((MD + 4 * DD) / 1024), thr>>>(x, W_qkv, W_out, xr, wqr, wor);

    // 1) symmetrize + zero-diag both G's (fp16)
    symzero2<<<(unsigned)(2 * DD / 256), thr>>>(Gq_raw, Gk_raw, G2h);

    // 2) QKV projections + fused LCA iteration 1 (z<2 writes vs, a0)
    {
        dim3 g(D_SZ / 128, M_SZ / 128, 3);
        mm_f16<MODE_QKV><<<g, thr, GSMEM_BYTES>>>(xr, wqr, u3, D_SZ, D_SZ, D_SZ, D_SZ, 1.f,
                                                  0, DD, MD, nullptr, vs, ab[0],
                                                  loglam_q, loglam_k);
    }

    // fork: V' GEMM runs on s2, overlapped with the whole LCA chain
    cudaEventRecord(evFork, 0);
    cudaStreamWaitEvent(s2, evFork, 0);

    // 3) V'^T = W_out . V^T (NT) -> [B][D][T] fp16  [stream s2]
    {
        dim3 g(T_SZ / 128, D_SZ / 128, B_SZ);
        mm_f16<MODE_VP><<<g, thr, GSMEM_BYTES, s2>>>(wor, vvv, vpt, D_SZ, D_SZ, D_SZ, T_SZ, 1.f,
                                                     0, TD, TD, nullptr, nullptr, nullptr,
                                                     nullptr, nullptr);
    }
    cudaEventRecord(evJoin, s2);

    // 4) LCA iterations 2..3: SPARSE (a nearly empty)   [stream 0]
    int cur = 0;
    {
        const unsigned g = (unsigned)(2 * M_SZ / 8);   // warp per row, 8 warps/CTA
        for (int it = 0; it < LCA_SPARSE_ITERS; it++) {
            lca_sparse<<<g, thr>>>(ab[cur], G2h, u3, vs, ab[cur ^ 1], loglam_q, loglam_k);
            cur ^= 1;
        }
    }

    // 5) LCA iterations 4..10: dense fp16 tensor GEMM + prox, q+k merged over z
    {
        dim3 g(D_SZ / 128, M_SZ / 128, 2);
        for (int it = 0; it < LCA_DENSE_ITERS; it++) {
            mm_f16<MODE_LCA><<<g, thr, GSMEM_BYTES>>>(ab[cur], G2h, ab[cur ^ 1],
                                                      D_SZ, D_SZ, D_SZ, D_SZ, 1.f,
                                                      MD, DD, MD, u3, vs, nullptr,
                                                      loglam_q, loglam_k);
            cur ^= 1;
        }
    }
    __half* qf = ab[cur];
    __half* kf = ab[cur] + MD;

    // 6) scores S = q k^T / 32, triangular grid (136 live tiles x batch), fp32 out
    {
        dim3 g(136, 1, B_SZ);
        mm_f16<MODE_SCORE><<<g, thr, GSMEM_BYTES>>>(qf, kf, S, D_SZ, D_SZ, D_SZ, T_SZ, 0.03125f,
                                                    TD, TD, TT, nullptr, nullptr, nullptr,
                                                    nullptr, nullptr);
    }

    // 7) causal softmax: fp32 scores -> fp16 probs (single pass)
    {
        dim3 g(T_SZ, B_SZ);
        softmax_causal<<<g, thr>>>(S, Ph);
    }

    // join: V' must be done before the final PV GEMM
    cudaStreamWaitEvent(0, evJoin, 0);

    // 8) out = P . V'^T (NT, causal K-limit), fp32 straight to output
    {
        dim3 g(D_SZ / 128, T_SZ / 128, B_SZ);
        mm_f16<MODE_PV><<<g, thr, GSMEM_BYTES>>>(Ph, vpt, out, T_SZ, T_SZ, T_SZ, D_SZ, 1.f,
                                                 TT, TD, TD, nullptr, nullptr, nullptr,
                                                 nullptr, nullptr);
    }
}